// round 7
// baseline (speedup 1.0000x reference)
#include <cuda_runtime.h>

#define CO 256
#define CI 256
#define NW 12      // number of (k,d) combos
#define HEAD 28    // S - (S+1)/2, S = 57

struct WPtrs { const float* w[NW]; };

// coef = softmax(alpha + gumbels); log_softmax drops (shift-invariant).
__device__ __forceinline__ void softmax12(const float* __restrict__ alpha,
                                          const float* __restrict__ gum,
                                          float* coef) {
    float l[NW];
    float m = -1e30f;
    #pragma unroll
    for (int i = 0; i < NW; i++) {
        l[i] = alpha[i] + gum[i];
        m = fmaxf(m, l[i]);
    }
    float s = 0.0f;
    #pragma unroll
    for (int i = 0; i < NW; i++) {
        l[i] = __expf(l[i] - m);
        s += l[i];
    }
    const float inv = 1.0f / s;
    #pragma unroll
    for (int i = 0; i < NW; i++) coef[i] = l[i] * inv;
}

// After the memset zeroes the whole output, each row only needs its 23
// nonzero elements stored. acc position s maps to:
//   s <= 28  ->  j = 28 - s          (head)
//   s >= 29  ->  j = N + 28 - s      (tail)
// One thread per row, fully straight-line, no shared, no syncs, N-generic
// (requires only N >= 57, guaranteed since output is padded up to input_size >= S).
__global__ void __launch_bounds__(256)
scatter_kernel(WPtrs wp,
               const float* __restrict__ alpha,
               const float* __restrict__ gum,
               float* __restrict__ out,
               int N) {
    const unsigned row = blockIdx.x * 256u + threadIdx.x;

    float C[NW];
    softmax12(alpha, gum, C);

    // Load all 72 taps for this row (weights are L2-resident: 18.9 MB total)
    float a[3], b[3], c[3], d[5], e[5], f[5], g[7], h[7], p[7];
    float q[9], r10[9], s9[9];
    {
        const float* w0  = wp.w[0]  + row * 3u;
        const float* w1  = wp.w[1]  + row * 3u;
        const float* w2  = wp.w[2]  + row * 3u;
        const float* w3  = wp.w[3]  + row * 5u;
        const float* w4  = wp.w[4]  + row * 5u;
        const float* w5  = wp.w[5]  + row * 5u;
        const float* w6  = wp.w[6]  + row * 7u;
        const float* w7  = wp.w[7]  + row * 7u;
        const float* w8  = wp.w[8]  + row * 7u;
        const float* w9  = wp.w[9]  + row * 9u;
        const float* w10 = wp.w[10] + row * 9u;
        const float* w11 = wp.w[11] + row * 9u;
        #pragma unroll
        for (int t = 0; t < 3; t++) { a[t]=__ldg(w0+t); b[t]=__ldg(w1+t); c[t]=__ldg(w2+t); }
        #pragma unroll
        for (int t = 0; t < 5; t++) { d[t]=__ldg(w3+t); e[t]=__ldg(w4+t); f[t]=__ldg(w5+t); }
        #pragma unroll
        for (int t = 0; t < 7; t++) { g[t]=__ldg(w6+t); h[t]=__ldg(w7+t); p[t]=__ldg(w8+t); }
        #pragma unroll
        for (int t = 0; t < 9; t++) { q[t]=__ldg(w9+t); r10[t]=__ldg(w10+t); s9[t]=__ldg(w11+t); }
    }

    // 23 nonzero acc positions (tap -> s map resolved at compile time):
    const float A0  = C[11]*s9[0];
    const float A7  = C[8]*p[0] + C[11]*s9[1];
    const float A14 = C[5]*f[0] + C[8]*p[1] + C[11]*s9[2];
    const float A16 = C[10]*r10[0];
    const float A19 = C[7]*h[0] + C[10]*r10[1];
    const float A21 = C[2]*c[0] + C[5]*f[1] + C[8]*p[2] + C[11]*s9[3];
    const float A22 = C[4]*e[0] + C[7]*h[1] + C[10]*r10[2];
    const float A24 = C[9]*q[0];
    const float A25 = C[1]*b[0] + C[4]*e[1] + C[6]*g[0] + C[7]*h[2] + C[9]*q[1] + C[10]*r10[3];
    const float A26 = C[3]*d[0] + C[6]*g[1] + C[9]*q[2];
    const float A27 = C[0]*a[0] + C[3]*d[1] + C[6]*g[2] + C[9]*q[3];
    const float A28 = C[0]*a[1] + C[1]*b[1] + C[2]*c[1] + C[3]*d[2] + C[4]*e[2] + C[5]*f[2]
                    + C[6]*g[3] + C[7]*h[3] + C[8]*p[3] + C[9]*q[4] + C[10]*r10[4] + C[11]*s9[4];
    const float A29 = C[0]*a[2] + C[3]*d[3] + C[6]*g[4] + C[9]*q[5];
    const float A30 = C[3]*d[4] + C[6]*g[5] + C[9]*q[6];
    const float A31 = C[1]*b[2] + C[4]*e[3] + C[6]*g[6] + C[7]*h[4] + C[9]*q[7] + C[10]*r10[5];
    const float A32 = C[9]*q[8];
    const float A34 = C[4]*e[4] + C[7]*h[5] + C[10]*r10[6];
    const float A35 = C[2]*c[2] + C[5]*f[3] + C[8]*p[4] + C[11]*s9[5];
    const float A37 = C[7]*h[6] + C[10]*r10[7];
    const float A40 = C[10]*r10[8];
    const float A42 = C[5]*f[4] + C[8]*p[5] + C[11]*s9[6];
    const float A49 = C[8]*p[6] + C[11]*s9[7];
    const float A56 = C[11]*s9[8];

    float* o = out + (size_t)row * (unsigned)N;

    // Head: j = 28 - s for s in {0,7,14,16,19,21,22,24,25,26,27,28}
    o[0]  = A28;  o[1]  = A27;  o[2]  = A26;  o[3]  = A25;
    o[4]  = A24;  o[6]  = A22;  o[7]  = A21;  o[9]  = A19;
    o[12] = A16;  o[14] = A14;  o[21] = A7;   o[28] = A0;
    // Tail: j = N + 28 - s for s in {29,...,56}
    float* t = o + N;
    t[-1]  = A29;  t[-2]  = A30;  t[-3]  = A31;  t[-4]  = A32;
    t[-6]  = A34;  t[-7]  = A35;  t[-9]  = A37;  t[-12] = A40;
    t[-14] = A42;  t[-21] = A49;  t[-28] = A56;
}

extern "C" void kernel_launch(void* const* d_in, const int* in_sizes, int n_in,
                              void* d_out, int out_size) {
    WPtrs wp;
    for (int i = 0; i < NW; i++) wp.w[i] = (const float*)d_in[i];
    const float* alpha = (const float*)d_in[12];
    const float* gum   = (const float*)d_in[13];
    const int N = out_size / (CO * CI);   // input_size, recovered host-side

    float* out = (float*)d_out;
    // 1) Bulk-zero the whole output via the driver fill path (graph memset node).
    cudaMemsetAsync(out, 0, (size_t)out_size * sizeof(float), 0);
    // 2) Write only the 23 nonzero elements per row (stream-ordered after memset).
    scatter_kernel<<<(CO * CI) / 256, 256>>>(wp, alpha, gum, out, N);
}